// round 6
// baseline (speedup 1.0000x reference)
#include <cuda_runtime.h>
#include <math.h>

// ---------------------------------------------------------------------------
// Wavelet scattering, T=16384, B=16, n1=64, n2=8, P=224, stride 256.
//
// R6: twiddle factors w1^r fetched directly from the e^{-2pi i k/N} table
// (index tb*r) instead of a 15-deep serial cmul chain -> breaks the longest
// dependency chain and cuts ~56 FMA instr per butterfly. Structure otherwise
// as R5: 4-pass radix-16, SoA shared + padding, fused gmem boundary passes,
// real-input first forward pass, time-domain phi lowpass.
// ---------------------------------------------------------------------------

#define T_N    16384
#define B_N    16
#define N1     64
#define N2     8
#define P_N    224
#define M_OUT  64
#define W_PHI  512
#define NPAD   (T_N + 1024)           // padded float array length
#define SMEM_BYTES ((2 * NPAD + W_PHI + 4) * (int)sizeof(float))

#define S1_BASE 1024
#define S2_BASE 66560

// ----------------------- device scratch ------------------------------------
static __device__ float2 g_xh[B_N * T_N];                     // 2 MB  (permuted)
static __device__ float2 g_u1h[(size_t)B_N * N1 * T_N];       // 128 MB (permuted)
static __device__ float  g_psi1p[N1 * T_N];                   // permuted, /N
static __device__ float  g_psi2p[N2 * T_N];
static __device__ float2 g_tw[T_N];                           // e^{-2pi i k/N}
static __device__ float  g_phit[W_PHI + 1];

// ----------------------- helpers -------------------------------------------
__device__ __forceinline__ int adr(int i) { return i + ((i >> 6) << 2); }

__device__ __forceinline__ float2 cmul(float2 a, float2 b) {
    return make_float2(fmaf(a.x, b.x, -a.y * b.y),
                       fmaf(a.x, b.y,  a.y * b.x));
}
// a * conj(b)
__device__ __forceinline__ float2 cmulc(float2 a, float2 b) {
    return make_float2(fmaf(a.x, b.x,  a.y * b.y),
                       fmaf(a.y, b.x, -a.x * b.y));
}

__device__ __forceinline__ float2 twf(float2 z, float c, float s) {
    return make_float2(fmaf(z.x, c,  z.y * s), fmaf(z.y, c, -z.x * s));
}
__device__ __forceinline__ float2 twi(float2 z, float c, float s) {
    return make_float2(fmaf(z.x, c, -z.y * s), fmaf(z.y, c,  z.x * s));
}

__device__ __forceinline__ void r4f(float2& A, float2& B, float2& C, float2& D) {
    float t0x = A.x + C.x, t0y = A.y + C.y, t1x = A.x - C.x, t1y = A.y - C.y;
    float t2x = B.x + D.x, t2y = B.y + D.y, t3x = B.x - D.x, t3y = B.y - D.y;
    A.x = t0x + t2x; A.y = t0y + t2y;  C.x = t0x - t2x; C.y = t0y - t2y;
    B.x = t1x + t3y; B.y = t1y - t3x;  D.x = t1x - t3y; D.y = t1y + t3x;
}
__device__ __forceinline__ void r4i(float2& A, float2& B, float2& C, float2& D) {
    float t0x = A.x + C.x, t0y = A.y + C.y, t1x = A.x - C.x, t1y = A.y - C.y;
    float t2x = B.x + D.x, t2y = B.y + D.y, t3x = B.x - D.x, t3y = B.y - D.y;
    A.x = t0x + t2x; A.y = t0y + t2y;  C.x = t0x - t2x; C.y = t0y - t2y;
    B.x = t1x - t3y; B.y = t1y + t3x;  D.x = t1x + t3y; D.y = t1y - t3x;
}

#define C16_1 0.9238795325112867f
#define S16_1 0.3826834323650898f
#define RSQ2  0.7071067811865476f

// 16-point DFT, natural input, base-4-digit-reversed register output.
__device__ __forceinline__ void dft16f(float2 a[16]) {
    r4f(a[0], a[4], a[8], a[12]); r4f(a[1], a[5], a[9], a[13]);
    r4f(a[2], a[6], a[10], a[14]); r4f(a[3], a[7], a[11], a[15]);
    a[5]  = twf(a[5],  C16_1,  S16_1);
    a[9]  = twf(a[9],  RSQ2,   RSQ2);
    a[13] = twf(a[13], S16_1,  C16_1);
    a[6]  = twf(a[6],  RSQ2,   RSQ2);
    a[10] = make_float2(a[10].y, -a[10].x);
    a[14] = twf(a[14], -RSQ2,   RSQ2);
    a[7]  = twf(a[7],  S16_1,  C16_1);
    a[11] = twf(a[11], -RSQ2,   RSQ2);
    a[15] = twf(a[15], -C16_1, -S16_1);
    r4f(a[0], a[1], a[2], a[3]);   r4f(a[4], a[5], a[6], a[7]);
    r4f(a[8], a[9], a[10], a[11]); r4f(a[12], a[13], a[14], a[15]);
}
__device__ __forceinline__ void dft16i(float2 a[16]) {
    r4i(a[0], a[4], a[8], a[12]); r4i(a[1], a[5], a[9], a[13]);
    r4i(a[2], a[6], a[10], a[14]); r4i(a[3], a[7], a[11], a[15]);
    a[5]  = twi(a[5],  C16_1,  S16_1);
    a[9]  = twi(a[9],  RSQ2,   RSQ2);
    a[13] = twi(a[13], S16_1,  C16_1);
    a[6]  = twi(a[6],  RSQ2,   RSQ2);
    a[10] = make_float2(-a[10].y, a[10].x);
    a[14] = twi(a[14], -RSQ2,   RSQ2);
    a[7]  = twi(a[7],  S16_1,  C16_1);
    a[11] = twi(a[11], -RSQ2,   RSQ2);
    a[15] = twi(a[15], -C16_1, -S16_1);
    r4i(a[0], a[1], a[2], a[3]);   r4i(a[4], a[5], a[6], a[7]);
    r4i(a[8], a[9], a[10], a[11]); r4i(a[12], a[13], a[14], a[15]);
}

// Forward radix-16 stage; twiddles w1^r looked up at g_tw[tb*r].
__device__ __forceinline__ void bf16_fwd(float* __restrict__ re, float* __restrict__ im,
                                         int bp, int stride, int tb) {
    float2 a[16];
#pragma unroll
    for (int m = 0; m < 16; m++) {
        int A_ = adr(bp + stride * m);
        a[m] = make_float2(re[A_], im[A_]);
    }
    dft16f(a);
    { int A_ = adr(bp); re[A_] = a[0].x; im[A_] = a[0].y; }
#pragma unroll
    for (int r = 1; r < 16; r++) {
        int p = ((r & 3) << 2) | (r >> 2);
        float2 w = g_tw[tb * r];
        float2 v = cmul(a[p], w);
        int A_ = adr(bp + stride * r);
        re[A_] = v.x; im[A_] = v.y;
    }
}

// Forward radix-16 stage, REAL input (im assumed zero, not read).
__device__ __forceinline__ void bf16_fwd_real(float* __restrict__ re, float* __restrict__ im,
                                              int bp, int stride, int tb) {
    float2 a[16];
#pragma unroll
    for (int m = 0; m < 16; m++) {
        int A_ = adr(bp + stride * m);
        a[m] = make_float2(re[A_], 0.f);
    }
    dft16f(a);
    { int A_ = adr(bp); re[A_] = a[0].x; im[A_] = a[0].y; }
#pragma unroll
    for (int r = 1; r < 16; r++) {
        int p = ((r & 3) << 2) | (r >> 2);
        float2 w = g_tw[tb * r];
        float2 v = cmul(a[p], w);
        int A_ = adr(bp + stride * r);
        re[A_] = v.x; im[A_] = v.y;
    }
}

// Inverse radix-16 stage; un-twiddle by conj(g_tw[tb*r]).
// ABS: store |X| into re only (im left stale/unused).
template<bool ABS>
__device__ __forceinline__ void bf16_inv(float* __restrict__ re, float* __restrict__ im,
                                         int bp, int stride, int tb) {
    float2 a[16];
#pragma unroll
    for (int r = 0; r < 16; r++) {
        int A_ = adr(bp + stride * r);
        a[r] = make_float2(re[A_], im[A_]);
    }
#pragma unroll
    for (int r = 1; r < 16; r++) {
        float2 w = g_tw[tb * r];
        a[r] = cmulc(a[r], w);
    }
    dft16i(a);
#pragma unroll
    for (int m = 0; m < 16; m++) {
        int p = ((m & 3) << 2) | (m >> 2);
        int A_ = adr(bp + stride * m);
        if (ABS) {
            re[A_] = sqrtf(fmaf(a[p].x, a[p].x, a[p].y * a[p].y));
        } else {
            re[A_] = a[p].x; im[A_] = a[p].y;
        }
    }
}

// Final forward radix-4 stage: shared -> gmem (permuted order), no twiddles.
__device__ __forceinline__ void pass4_fwd(const float* __restrict__ re,
                                          const float* __restrict__ im,
                                          int t, float2* __restrict__ dst) {
#pragma unroll
    for (int h = 0; h < 4; h++) {
        int i0 = 4 * (t + 1024 * h);
        int A0 = adr(i0);
        float4 rr = *(const float4*)(re + A0);
        float4 ii = *(const float4*)(im + A0);
        float2 A = make_float2(rr.x, ii.x), B = make_float2(rr.y, ii.y);
        float2 C = make_float2(rr.z, ii.z), D = make_float2(rr.w, ii.w);
        r4f(A, B, C, D);
        float4* dp = (float4*)(dst + i0);
        dp[0] = make_float4(A.x, A.y, B.x, B.y);
        dp[1] = make_float4(C.x, C.y, D.x, D.y);
    }
}

// Entry inverse radix-4 stage: gmem * psi -> shared, no twiddles.
__device__ __forceinline__ void pass4_inv(float* __restrict__ re, float* __restrict__ im,
                                          int t, const float2* __restrict__ src,
                                          const float* __restrict__ psi) {
#pragma unroll
    for (int h = 0; h < 4; h++) {
        int i0 = 4 * (t + 1024 * h);
        const float4* sp = (const float4*)(src + i0);
        float4 v1 = sp[0], v2 = sp[1];
        float4 p4 = *(const float4*)(psi + i0);
        float2 A = make_float2(v1.x * p4.x, v1.y * p4.x);
        float2 B = make_float2(v1.z * p4.y, v1.w * p4.y);
        float2 C = make_float2(v2.x * p4.z, v2.y * p4.z);
        float2 D = make_float2(v2.z * p4.w, v2.w * p4.w);
        r4i(A, B, C, D);
        int A0 = adr(i0);
        *(float4*)(re + A0) = make_float4(A.x, B.x, C.x, D.x);
        *(float4*)(im + A0) = make_float4(A.y, B.y, C.y, D.y);
    }
}

// 3 inner forward passes (strides 1024, 64, 4). REAL_IN: first pass reads re only.
template<bool REAL_IN>
__device__ __forceinline__ void fwd3(float* re, float* im, int t) {
    if (REAL_IN) bf16_fwd_real(re, im, t, 1024, t);
    else         bf16_fwd     (re, im, t, 1024, t);
    __syncthreads();
    bf16_fwd(re, im, ((t >> 6) << 10) + (t & 63), 64, (t & 63) << 4);
    __syncthreads();
    bf16_fwd(re, im, ((t >> 2) << 6) + (t & 3), 4, (t & 3) << 8);
    __syncthreads();
}

// 3 inner inverse passes (strides 4, 64, 1024); last optionally takes |.|
template<bool ABS>
__device__ __forceinline__ void inv3(float* re, float* im, int t) {
    bf16_inv<false>(re, im, ((t >> 2) << 6) + (t & 3), 4, (t & 3) << 8);
    __syncthreads();
    bf16_inv<false>(re, im, ((t >> 6) << 10) + (t & 63), 64, (t & 63) << 4);
    __syncthreads();
    bf16_inv<ABS>(re, im, t, 1024, t);
    __syncthreads();
}

// Time-domain lowpass + downsample by 256 (reads padded re array).
__device__ __forceinline__ void lowpass64(const float* __restrict__ re,
                                          const float* __restrict__ ph,
                                          float* __restrict__ outp) {
    const int lane = threadIdx.x & 31;
    const int warp = threadIdx.x >> 5;
    for (int m = warp; m < M_OUT; m += 32) {
        const int t0 = m << 8;
        float acc = 0.f;
        for (int dd = lane; dd <= 2 * W_PHI; dd += 32) {
            const int d   = dd - W_PHI;
            const int ad  = d < 0 ? -d : d;
            const int idx = (t0 - d + T_N) & (T_N - 1);
            acc = fmaf(re[adr(idx)], ph[ad], acc);
        }
#pragma unroll
        for (int off = 16; off; off >>= 1)
            acc += __shfl_down_sync(0xffffffffu, acc, off);
        if (lane == 0) outp[m] = acc;
    }
}

// ----------------------- init kernels ---------------------------------------
__device__ __forceinline__ int posrm(int k) {
    return ((k & 15) << 10) | (((k >> 4) & 15) << 6) | (((k >> 8) & 15) << 2) | (k >> 12);
}

__global__ void k_init(const float* __restrict__ psi1, const float* __restrict__ psi2) {
    const float invN = 1.0f / (float)T_N;
    const int total = N1 * T_N;
    for (int i = blockIdx.x * blockDim.x + threadIdx.x; i < total;
         i += gridDim.x * blockDim.x) {
        const int k = i & (T_N - 1);
        const int j = i >> 14;
        const int pos = posrm(k);
        g_psi1p[(j << 14) + pos] = psi1[i] * invN;
        if (j < N2) g_psi2p[(j << 14) + pos] = psi2[i] * invN;
        if (j == 0) {
            float sn, cn;
            sincospif(-2.0f * (float)k / (float)T_N, &sn, &cn);
            g_tw[k] = make_float2(cn, sn);
        }
    }
}

__global__ void k_phit(const float* __restrict__ phi) {
    __shared__ float red[256];
    const int n = blockIdx.x;   // 0..W_PHI
    float acc = 0.f;
    for (int k = threadIdx.x; k < T_N; k += blockDim.x)
        acc = fmaf(phi[k], g_tw[(k * n) & (T_N - 1)].x, acc);
    red[threadIdx.x] = acc;
    __syncthreads();
    for (int off = 128; off; off >>= 1) {
        if (threadIdx.x < off) red[threadIdx.x] += red[threadIdx.x + off];
        __syncthreads();
    }
    if (threadIdx.x == 0) g_phit[n] = red[0] * (1.0f / (float)T_N);
}

// ----------------------- main kernels ---------------------------------------
__global__ void __launch_bounds__(1024, 1)
k_xfft(const float* __restrict__ x, float* __restrict__ out) {
    extern __shared__ float sm[];
    float* re = sm; float* im = sm + NPAD; float* ph = sm + 2 * NPAD;
    const int b = blockIdx.x, t = threadIdx.x;
    for (int i = t; i <= W_PHI; i += 1024) ph[i] = g_phit[i];
    const float* xb = x + b * T_N;
    for (int i = t; i < T_N; i += 1024) re[adr(i)] = xb[i];
    __syncthreads();
    lowpass64(re, ph, out + b * M_OUT);                 // S0
    __syncthreads();
    fwd3<true>(re, im, t);
    pass4_fwd(re, im, t, g_xh + b * T_N);
}

__global__ void __launch_bounds__(1024, 1)
k_order1(float* __restrict__ out) {
    extern __shared__ float sm[];
    float* re = sm; float* im = sm + NPAD; float* ph = sm + 2 * NPAD;
    const int j1 = blockIdx.x, b = blockIdx.y, t = threadIdx.x;
    for (int i = t; i <= W_PHI; i += 1024) ph[i] = g_phit[i];
    pass4_inv(re, im, t, g_xh + b * T_N, g_psi1p + j1 * T_N);
    __syncthreads();
    inv3<true>(re, im, t);                               // |ifft| -> re
    lowpass64(re, ph, out + S1_BASE + (b * N1 + j1) * M_OUT);   // S1
    __syncthreads();
    fwd3<true>(re, im, t);
    pass4_fwd(re, im, t, g_u1h + (size_t)(b * N1 + j1) * T_N);
}

__global__ void __launch_bounds__(1024, 1)
k_order2(const int* __restrict__ pj1, const int* __restrict__ pj2,
         float* __restrict__ out) {
    extern __shared__ float sm[];
    float* re = sm; float* im = sm + NPAD; float* ph = sm + 2 * NPAD;
    const int idx = blockIdx.x, t = threadIdx.x;
    const int b = idx / P_N;
    const int p = idx - b * P_N;
    const int j1 = pj1[p], j2 = pj2[p];
    for (int i = t; i <= W_PHI; i += 1024) ph[i] = g_phit[i];
    pass4_inv(re, im, t, g_u1h + (size_t)(b * N1 + j1) * T_N, g_psi2p + j2 * T_N);
    __syncthreads();
    inv3<true>(re, im, t);
    lowpass64(re, ph, out + S2_BASE + (b * P_N + p) * M_OUT);   // S2
}

// ----------------------- launch --------------------------------------------
extern "C" void kernel_launch(void* const* d_in, const int* in_sizes, int n_in,
                              void* d_out, int out_size) {
    (void)in_sizes; (void)n_in; (void)out_size;
    const float* x    = (const float*)d_in[0];
    const float* psi1 = (const float*)d_in[1];
    const float* psi2 = (const float*)d_in[2];
    const float* phi  = (const float*)d_in[3];
    const int*   pj1  = (const int*)d_in[4];
    const int*   pj2  = (const int*)d_in[5];
    float* out = (float*)d_out;

    cudaFuncSetAttribute(k_xfft,   cudaFuncAttributeMaxDynamicSharedMemorySize, SMEM_BYTES);
    cudaFuncSetAttribute(k_order1, cudaFuncAttributeMaxDynamicSharedMemorySize, SMEM_BYTES);
    cudaFuncSetAttribute(k_order2, cudaFuncAttributeMaxDynamicSharedMemorySize, SMEM_BYTES);

    k_init<<<256, 256>>>(psi1, psi2);
    k_phit<<<W_PHI + 1, 256>>>(phi);
    k_xfft<<<B_N, 1024, SMEM_BYTES>>>(x, out);
    dim3 g1(N1, B_N);
    k_order1<<<g1, 1024, SMEM_BYTES>>>(out);
    k_order2<<<B_N * P_N, 1024, SMEM_BYTES>>>(pj1, pj2, out);
}

// round 7
// speedup vs baseline: 1.5527x; 1.5527x over previous
#include <cuda_runtime.h>
#include <math.h>

// ---------------------------------------------------------------------------
// Wavelet scattering, T=16384, B=16, n1=64, n2=8, P=224, stride 256.
//
// R7: radix-8 x4 + boundary radix-4 (no spills at 1024 thr), twiddle base
// from small shared tables (conflict-free), powers via depth-2 register tree.
// Pad 4-per-32 shared layout, conflict-free for every stride class.
// ---------------------------------------------------------------------------

#define T_N    16384
#define B_N    16
#define N1     64
#define N2     8
#define P_N    224
#define M_OUT  64
#define W_PHI  512
#define NPAD   (T_N + 2048)            // i + ((i>>5)<<2) padding
#define NTW    (2048 + 256 + 32 + 4)
#define SMEM_BYTES ((2 * NPAD + 2 * NTW + W_PHI + 8) * (int)sizeof(float))

#define S1_BASE 1024
#define S2_BASE 66560

// ----------------------- device scratch ------------------------------------
static __device__ float2 g_xh[B_N * T_N];                     // permuted
static __device__ float2 g_u1h[(size_t)B_N * N1 * T_N];       // permuted
static __device__ float  g_psi1p[N1 * T_N];                   // permuted, /N
static __device__ float  g_psi2p[N2 * T_N];
static __device__ float2 g_tw[T_N];                           // e^{-2pi i k/N}
static __device__ float  g_phit[W_PHI + 1];

// ----------------------- helpers -------------------------------------------
__device__ __forceinline__ int adr(int i) { return i + ((i >> 5) << 2); }

__device__ __forceinline__ float2 cmul(float2 a, float2 b) {
    return make_float2(fmaf(a.x, b.x, -a.y * b.y),
                       fmaf(a.x, b.y,  a.y * b.x));
}
// a * conj(b)
__device__ __forceinline__ float2 cmulc(float2 a, float2 b) {
    return make_float2(fmaf(a.x, b.x,  a.y * b.y),
                       fmaf(a.y, b.x, -a.x * b.y));
}

__device__ __forceinline__ void r4f(float2& A, float2& B, float2& C, float2& D) {
    float t0x = A.x + C.x, t0y = A.y + C.y, t1x = A.x - C.x, t1y = A.y - C.y;
    float t2x = B.x + D.x, t2y = B.y + D.y, t3x = B.x - D.x, t3y = B.y - D.y;
    A.x = t0x + t2x; A.y = t0y + t2y;  C.x = t0x - t2x; C.y = t0y - t2y;
    B.x = t1x + t3y; B.y = t1y - t3x;  D.x = t1x - t3y; D.y = t1y + t3x;
}
__device__ __forceinline__ void r4i(float2& A, float2& B, float2& C, float2& D) {
    float t0x = A.x + C.x, t0y = A.y + C.y, t1x = A.x - C.x, t1y = A.y - C.y;
    float t2x = B.x + D.x, t2y = B.y + D.y, t3x = B.x - D.x, t3y = B.y - D.y;
    A.x = t0x + t2x; A.y = t0y + t2y;  C.x = t0x - t2x; C.y = t0y - t2y;
    B.x = t1x - t3y; B.y = t1y + t3x;  D.x = t1x + t3y; D.y = t1y - t3x;
}

#define RSQ2 0.7071067811865476f

// Forward radix-8 stage. REAL: imag input assumed zero (not read).
// Loads a[m] at base+L*m, stores DFT8 bin r times w1^r at base+L*r.
template<bool REAL>
__device__ __forceinline__ void bf8_fwd(float* __restrict__ re, float* __restrict__ im,
                                        int base, int L, float2 w1) {
    float2 a[8];
#pragma unroll
    for (int m = 0; m < 8; m++) {
        int A_ = adr(base + L * m);
        a[m] = make_float2(re[A_], REAL ? 0.f : im[A_]);
    }
    float2 s0, s1, s2, s3, d0, d1, d2, d3;
    s0 = make_float2(a[0].x + a[4].x, a[0].y + a[4].y);
    s1 = make_float2(a[1].x + a[5].x, a[1].y + a[5].y);
    s2 = make_float2(a[2].x + a[6].x, a[2].y + a[6].y);
    s3 = make_float2(a[3].x + a[7].x, a[3].y + a[7].y);
    d0 = make_float2(a[0].x - a[4].x, a[0].y - a[4].y);
    float2 e1 = make_float2(a[1].x - a[5].x, a[1].y - a[5].y);
    float2 e2 = make_float2(a[2].x - a[6].x, a[2].y - a[6].y);
    float2 e3 = make_float2(a[3].x - a[7].x, a[3].y - a[7].y);
    d1 = make_float2((e1.x + e1.y) * RSQ2, (e1.y - e1.x) * RSQ2);   // *(1-i)/s2
    d2 = make_float2(e2.y, -e2.x);                                  // *(-i)
    d3 = make_float2((e3.y - e3.x) * RSQ2, -(e3.x + e3.y) * RSQ2);  // *(-(1+i)/s2)
    r4f(s0, s1, s2, s3);   // bins 0,2,4,6
    r4f(d0, d1, d2, d3);   // bins 1,3,5,7
    float2 y[8] = {s0, d0, s1, d1, s2, d2, s3, d3};
    float2 w2 = cmul(w1, w1), w4 = cmul(w2, w2);
    { int A_ = adr(base); re[A_] = y[0].x; im[A_] = y[0].y; }
#pragma unroll
    for (int r = 1; r < 8; r++) {
        float2 v = y[r];
        if (r & 1) v = cmul(v, w1);
        if (r & 2) v = cmul(v, w2);
        if (r & 4) v = cmul(v, w4);
        int A_ = adr(base + L * r);
        re[A_] = v.x; im[A_] = v.y;
    }
}

// Inverse radix-8 stage: loads bin r at base+L*r, un-twiddles by conj(w1)^r,
// IDFT8, stores x[m] at base+L*m. ABS: store |x| into re only.
template<bool ABS>
__device__ __forceinline__ void bf8_inv(float* __restrict__ re, float* __restrict__ im,
                                        int base, int L, float2 w1) {
    float2 y[8];
#pragma unroll
    for (int r = 0; r < 8; r++) {
        int A_ = adr(base + L * r);
        y[r] = make_float2(re[A_], im[A_]);
    }
    float2 w2 = cmul(w1, w1), w4 = cmul(w2, w2);
#pragma unroll
    for (int r = 1; r < 8; r++) {
        if (r & 1) y[r] = cmulc(y[r], w1);
        if (r & 2) y[r] = cmulc(y[r], w2);
        if (r & 4) y[r] = cmulc(y[r], w4);
    }
    float2 E0 = y[0], E1 = y[2], E2 = y[4], E3 = y[6];
    float2 O0 = y[1], O1 = y[3], O2 = y[5], O3 = y[7];
    r4i(E0, E1, E2, E3);
    r4i(O0, O1, O2, O3);
    float2 u0 = O0;
    float2 u1 = make_float2((O1.x - O1.y) * RSQ2, (O1.x + O1.y) * RSQ2);   // *(1+i)/s2
    float2 u2 = make_float2(-O2.y, O2.x);                                  // *(+i)
    float2 u3 = make_float2(-(O3.x + O3.y) * RSQ2, (O3.x - O3.y) * RSQ2);  // *(-1+i)/s2
    float2 X[8];
    X[0] = make_float2(E0.x + u0.x, E0.y + u0.y);
    X[1] = make_float2(E1.x + u1.x, E1.y + u1.y);
    X[2] = make_float2(E2.x + u2.x, E2.y + u2.y);
    X[3] = make_float2(E3.x + u3.x, E3.y + u3.y);
    X[4] = make_float2(E0.x - u0.x, E0.y - u0.y);
    X[5] = make_float2(E1.x - u1.x, E1.y - u1.y);
    X[6] = make_float2(E2.x - u2.x, E2.y - u2.y);
    X[7] = make_float2(E3.x - u3.x, E3.y - u3.y);
#pragma unroll
    for (int m = 0; m < 8; m++) {
        int A_ = adr(base + L * m);
        if (ABS) {
            re[A_] = sqrtf(fmaf(X[m].x, X[m].x, X[m].y * X[m].y));
        } else {
            re[A_] = X[m].x; im[A_] = X[m].y;
        }
    }
}

// Final forward radix-4 stage: shared -> gmem (permuted order), no twiddles.
__device__ __forceinline__ void pass4_fwd(const float* __restrict__ re,
                                          const float* __restrict__ im,
                                          int t, float2* __restrict__ dst) {
#pragma unroll
    for (int h = 0; h < 4; h++) {
        int i0 = 4 * (t + 1024 * h);
        int A0 = adr(i0);
        float4 rr = *(const float4*)(re + A0);
        float4 ii = *(const float4*)(im + A0);
        float2 A = make_float2(rr.x, ii.x), B = make_float2(rr.y, ii.y);
        float2 C = make_float2(rr.z, ii.z), D = make_float2(rr.w, ii.w);
        r4f(A, B, C, D);
        float4* dp = (float4*)(dst + i0);
        dp[0] = make_float4(A.x, A.y, B.x, B.y);
        dp[1] = make_float4(C.x, C.y, D.x, D.y);
    }
}

// Entry inverse radix-4 stage: gmem * psi -> shared, no twiddles.
__device__ __forceinline__ void pass4_inv(float* __restrict__ re, float* __restrict__ im,
                                          int t, const float2* __restrict__ src,
                                          const float* __restrict__ psi) {
#pragma unroll
    for (int h = 0; h < 4; h++) {
        int i0 = 4 * (t + 1024 * h);
        const float4* sp = (const float4*)(src + i0);
        float4 v1 = sp[0], v2 = sp[1];
        float4 p4 = *(const float4*)(psi + i0);
        float2 A = make_float2(v1.x * p4.x, v1.y * p4.x);
        float2 B = make_float2(v1.z * p4.y, v1.w * p4.y);
        float2 C = make_float2(v2.x * p4.z, v2.y * p4.z);
        float2 D = make_float2(v2.z * p4.w, v2.w * p4.w);
        r4i(A, B, C, D);
        int A0 = adr(i0);
        *(float4*)(re + A0) = make_float4(A.x, B.x, C.x, D.x);
        *(float4*)(im + A0) = make_float4(A.y, B.y, C.y, D.y);
    }
}

// Load shared twiddle tables (w1 values per stage; all indices < 2048 in g_tw).
__device__ __forceinline__ void load_tw(float2* tw, int t) {
    float2* tw1 = tw;            // [2048] : g_tw[j]
    float2* tw2 = tw + 2048;     // [256]  : g_tw[8j]
    float2* tw3 = tw + 2304;     // [32]   : g_tw[64j]
    float2* tw4 = tw + 2336;     // [4]    : g_tw[512j]
    for (int i = t; i < 2048; i += 1024) tw1[i] = g_tw[i];
    if (t < 256) tw2[t] = g_tw[8 * t];
    if (t < 32)  tw3[t] = g_tw[64 * t];
    if (t < 4)   tw4[t] = g_tw[512 * t];
}

// 4 forward radix-8 passes (L = 2048, 256, 32, 4). REAL: first pass real-only.
template<bool REAL>
__device__ __forceinline__ void fwd4(float* re, float* im, const float2* tw, int t) {
#pragma unroll
    for (int q = 0; q < 2; q++) { int i = t + 1024 * q; bf8_fwd<REAL>(re, im, i, 2048, tw[i]); }
    __syncthreads();
#pragma unroll
    for (int q = 0; q < 2; q++) {
        int i = t + 1024 * q;
        bf8_fwd<false>(re, im, ((i >> 8) << 11) + (i & 255), 256, tw[2048 + (i & 255)]);
    }
    __syncthreads();
#pragma unroll
    for (int q = 0; q < 2; q++) {
        int i = t + 1024 * q;
        bf8_fwd<false>(re, im, ((i >> 5) << 8) + (i & 31), 32, tw[2304 + (i & 31)]);
    }
    __syncthreads();
#pragma unroll
    for (int q = 0; q < 2; q++) {
        int i = t + 1024 * q;
        bf8_fwd<false>(re, im, ((i >> 2) << 5) + (i & 3), 4, tw[2336 + (i & 3)]);
    }
    __syncthreads();
}

// 4 inverse radix-8 passes (L = 4, 32, 256, 2048); last optionally |.|
template<bool ABS>
__device__ __forceinline__ void inv4(float* re, float* im, const float2* tw, int t) {
#pragma unroll
    for (int q = 0; q < 2; q++) {
        int i = t + 1024 * q;
        bf8_inv<false>(re, im, ((i >> 2) << 5) + (i & 3), 4, tw[2336 + (i & 3)]);
    }
    __syncthreads();
#pragma unroll
    for (int q = 0; q < 2; q++) {
        int i = t + 1024 * q;
        bf8_inv<false>(re, im, ((i >> 5) << 8) + (i & 31), 32, tw[2304 + (i & 31)]);
    }
    __syncthreads();
#pragma unroll
    for (int q = 0; q < 2; q++) {
        int i = t + 1024 * q;
        bf8_inv<false>(re, im, ((i >> 8) << 11) + (i & 255), 256, tw[2048 + (i & 255)]);
    }
    __syncthreads();
#pragma unroll
    for (int q = 0; q < 2; q++) { int i = t + 1024 * q; bf8_inv<ABS>(re, im, i, 2048, tw[i]); }
    __syncthreads();
}

// Time-domain lowpass + downsample by 256 (reads padded re array).
__device__ __forceinline__ void lowpass64(const float* __restrict__ re,
                                          const float* __restrict__ ph,
                                          float* __restrict__ outp) {
    const int lane = threadIdx.x & 31;
    const int warp = threadIdx.x >> 5;
    for (int m = warp; m < M_OUT; m += 32) {
        const int t0 = m << 8;
        float acc = 0.f;
        for (int dd = lane; dd <= 2 * W_PHI; dd += 32) {
            const int d   = dd - W_PHI;
            const int ad  = d < 0 ? -d : d;
            const int idx = (t0 - d + T_N) & (T_N - 1);
            acc = fmaf(re[adr(idx)], ph[ad], acc);
        }
#pragma unroll
        for (int off = 16; off; off >>= 1)
            acc += __shfl_down_sync(0xffffffffu, acc, off);
        if (lane == 0) outp[m] = acc;
    }
}

// ----------------------- init kernels ---------------------------------------
// frequency k -> stored position (8,8,8,8 digit reversal, top factor 4 last)
__device__ __forceinline__ int posrm8(int k) {
    return ((k & 7) << 11) | (((k >> 3) & 7) << 8) | (((k >> 6) & 7) << 5)
         | (((k >> 9) & 7) << 2) | (k >> 12);
}

__global__ void k_init(const float* __restrict__ psi1, const float* __restrict__ psi2) {
    const float invN = 1.0f / (float)T_N;
    const int total = N1 * T_N;
    for (int i = blockIdx.x * blockDim.x + threadIdx.x; i < total;
         i += gridDim.x * blockDim.x) {
        const int k = i & (T_N - 1);
        const int j = i >> 14;
        const int pos = posrm8(k);
        g_psi1p[(j << 14) + pos] = psi1[i] * invN;
        if (j < N2) g_psi2p[(j << 14) + pos] = psi2[i] * invN;
        if (j == 0) {
            float sn, cn;
            sincospif(-2.0f * (float)k / (float)T_N, &sn, &cn);
            g_tw[k] = make_float2(cn, sn);
        }
    }
}

__global__ void k_phit(const float* __restrict__ phi) {
    __shared__ float red[256];
    const int n = blockIdx.x;   // 0..W_PHI
    float acc = 0.f;
    for (int k = threadIdx.x; k < T_N; k += blockDim.x)
        acc = fmaf(phi[k], g_tw[(k * n) & (T_N - 1)].x, acc);
    red[threadIdx.x] = acc;
    __syncthreads();
    for (int off = 128; off; off >>= 1) {
        if (threadIdx.x < off) red[threadIdx.x] += red[threadIdx.x + off];
        __syncthreads();
    }
    if (threadIdx.x == 0) g_phit[n] = red[0] * (1.0f / (float)T_N);
}

// ----------------------- main kernels ---------------------------------------
__global__ void __launch_bounds__(1024, 1)
k_xfft(const float* __restrict__ x, float* __restrict__ out) {
    extern __shared__ float sm[];
    float* re = sm; float* im = sm + NPAD;
    float2* tw = (float2*)(sm + 2 * NPAD);
    float* ph = sm + 2 * NPAD + 2 * NTW;
    const int b = blockIdx.x, t = threadIdx.x;
    load_tw(tw, t);
    for (int i = t; i <= W_PHI; i += 1024) ph[i] = g_phit[i];
    const float* xb = x + b * T_N;
    for (int i = t; i < T_N; i += 1024) re[adr(i)] = xb[i];
    __syncthreads();
    lowpass64(re, ph, out + b * M_OUT);                 // S0
    __syncthreads();
    fwd4<true>(re, im, tw, t);
    pass4_fwd(re, im, t, g_xh + b * T_N);
}

__global__ void __launch_bounds__(1024, 1)
k_order1(float* __restrict__ out) {
    extern __shared__ float sm[];
    float* re = sm; float* im = sm + NPAD;
    float2* tw = (float2*)(sm + 2 * NPAD);
    float* ph = sm + 2 * NPAD + 2 * NTW;
    const int j1 = blockIdx.x, b = blockIdx.y, t = threadIdx.x;
    load_tw(tw, t);
    for (int i = t; i <= W_PHI; i += 1024) ph[i] = g_phit[i];
    pass4_inv(re, im, t, g_xh + b * T_N, g_psi1p + j1 * T_N);
    __syncthreads();
    inv4<true>(re, im, tw, t);                           // |ifft| -> re
    lowpass64(re, ph, out + S1_BASE + (b * N1 + j1) * M_OUT);   // S1
    __syncthreads();
    fwd4<true>(re, im, tw, t);
    pass4_fwd(re, im, t, g_u1h + (size_t)(b * N1 + j1) * T_N);
}

__global__ void __launch_bounds__(1024, 1)
k_order2(const int* __restrict__ pj1, const int* __restrict__ pj2,
         float* __restrict__ out) {
    extern __shared__ float sm[];
    float* re = sm; float* im = sm + NPAD;
    float2* tw = (float2*)(sm + 2 * NPAD);
    float* ph = sm + 2 * NPAD + 2 * NTW;
    const int idx = blockIdx.x, t = threadIdx.x;
    const int b = idx / P_N;
    const int p = idx - b * P_N;
    const int j1 = pj1[p], j2 = pj2[p];
    load_tw(tw, t);
    for (int i = t; i <= W_PHI; i += 1024) ph[i] = g_phit[i];
    pass4_inv(re, im, t, g_u1h + (size_t)(b * N1 + j1) * T_N, g_psi2p + j2 * T_N);
    __syncthreads();
    inv4<true>(re, im, tw, t);
    lowpass64(re, ph, out + S2_BASE + (b * P_N + p) * M_OUT);   // S2
}

// ----------------------- launch --------------------------------------------
extern "C" void kernel_launch(void* const* d_in, const int* in_sizes, int n_in,
                              void* d_out, int out_size) {
    (void)in_sizes; (void)n_in; (void)out_size;
    const float* x    = (const float*)d_in[0];
    const float* psi1 = (const float*)d_in[1];
    const float* psi2 = (const float*)d_in[2];
    const float* phi  = (const float*)d_in[3];
    const int*   pj1  = (const int*)d_in[4];
    const int*   pj2  = (const int*)d_in[5];
    float* out = (float*)d_out;

    cudaFuncSetAttribute(k_xfft,   cudaFuncAttributeMaxDynamicSharedMemorySize, SMEM_BYTES);
    cudaFuncSetAttribute(k_order1, cudaFuncAttributeMaxDynamicSharedMemorySize, SMEM_BYTES);
    cudaFuncSetAttribute(k_order2, cudaFuncAttributeMaxDynamicSharedMemorySize, SMEM_BYTES);

    k_init<<<256, 256>>>(psi1, psi2);
    k_phit<<<W_PHI + 1, 256>>>(phi);
    k_xfft<<<B_N, 1024, SMEM_BYTES>>>(x, out);
    dim3 g1(N1, B_N);
    k_order1<<<g1, 1024, SMEM_BYTES>>>(out);
    k_order2<<<B_N * P_N, 1024, SMEM_BYTES>>>(pj1, pj2, out);
}